// round 2
// baseline (speedup 1.0000x reference)
#include <cuda_runtime.h>
#include <cuda_bf16.h>

#define NUM_CLASSES 10

// One WARP per batch. Lanes 0..23 each own (channel, row) of the 3x8x8
// top-left patch and load the 8-float row as two float4 (LDG.128 x2).
// Butterfly shuffles give every lane the total; lanes 0..9 write the logits.
// No shared memory, no block barrier.
__global__ __launch_bounds__(32, 16)
void ldc_kernel(const float* __restrict__ x, float* __restrict__ out) {
    const int b    = blockIdx.x;        // batch 0..63
    const int lane = threadIdx.x;       // 0..31

    float v = 0.0f;
    if (lane < 24) {
        const int c = lane >> 3;        // channel 0..2
        const int r = lane & 7;         // row 0..7
        // x layout: [64, 3, 512, 512] row-major; row start is 16B-aligned.
        const float4* p = (const float4*)(x + (((long long)b * 3 + c) * 512 + r) * 512);
        float4 a0 = p[0];
        float4 a1 = p[1];
        v = ((a0.x + a0.y) + (a0.z + a0.w)) + ((a1.x + a1.y) + (a1.z + a1.w));
    }

    // Butterfly reduce: all lanes end with the full sum over 192 elements.
    #pragma unroll
    for (int off = 16; off > 0; off >>= 1)
        v += __shfl_xor_sync(0xFFFFFFFFu, v, off);

    const float mean = v / 192.0f;
    // Python int() truncates toward zero; % with positive modulus is non-negative.
    int t = (int)truncf(mean * 10.0f);
    int pred = t % NUM_CLASSES;
    if (pred < 0) pred += NUM_CLASSES;

    if (lane < NUM_CLASSES)
        out[b * NUM_CLASSES + lane] = (lane == pred) ? 10.0f : 0.0f;
}

extern "C" void kernel_launch(void* const* d_in, const int* in_sizes, int n_in,
                              void* d_out, int out_size) {
    const float* x = (const float*)d_in[0];
    float* out = (float*)d_out;
    ldc_kernel<<<64, 32>>>(x, out);
}